// round 8
// baseline (speedup 1.0000x reference)
#include <cuda_runtime.h>

#define WARPS 4
#define THREADS 128
#define NSTEP 10
#define XSTRIDE 48     // floats per padded row; conflict-free LDS.64
#define CAP 1600       // per-warp compacted capacity (elements); overflow -> exact fallback
#define SKIP_THR 0.1535f  // c <= this provably never spikes (c*6.51322 < 1)

__device__ __forceinline__ float setgt1(float a) {
    float r;
    asm("set.gt.f32.f32 %0, %1, %2;" : "=f"(r) : "f"(a), "f"(1.0f));
    return r;
}

// Two-phase SNN kernel, one warp per sample.
// Phase 1: conv for all 2048 elements; elements with c <= SKIP_THR can never
//          spike (m_t = c*sum(beta^k) <= c*6.51322 < 1) and contribute exact
//          +0 -> drop them. Active (c, idx) ballot-compacted into smem.
// Phase 2: 10-step membrane recurrence + FC accumulation over actives only,
//          2 independent elements per lane for latency hiding.
__global__ void __launch_bounds__(THREADS)
snn_kernel(const float* __restrict__ x, const float* __restrict__ convw,
           const float* __restrict__ convb, const float* __restrict__ fcw,
           const float* __restrict__ fcb, float* __restrict__ out, int nB)
{
    extern __shared__ float dsm[];
    float* sw01 = dsm;                     // 4096 f: interleaved (w0_i, w1_i)
    float* scw4 = sw01 + 4096;             // 96 f: per ch w0..w8, bias, pad
    float* sxall = scw4 + 96;              // 4 * 864 f: padded input tiles
    float* call = sxall + 4 * 864;         // 4 * CAP f: compacted c
    unsigned short* iall =
        (unsigned short*)(call + 4 * CAP); // 4 * CAP u16: compacted idx

    const int tid  = threadIdx.x;
    const int warp = tid >> 5;
    const int lane = tid & 31;
    const long long b = (long long)blockIdx.x * WARPS + warp;
    const unsigned FULL = 0xffffffffu;
    const unsigned lmlt = (1u << lane) - 1u;

    for (int i = tid; i < 2048; i += THREADS) {
        sw01[2 * i]     = fcw[i];
        sw01[2 * i + 1] = fcw[2048 + i];
    }
    if (tid < 96) {
        int ch = tid / 12, k = tid % 12;
        float v = 0.0f;
        if (k < 9)       v = convw[ch * 9 + k];
        else if (k == 9) v = convb[ch];
        scw4[tid] = v;
    }

    float* sxw = sxall + warp * 864;
    for (int i = lane; i < 864; i += 32) sxw[i] = 0.0f;
    __syncwarp();
    if (b < nB) {
        const float4* xb = (const float4*)(x + b * 256);
        #pragma unroll
        for (int i = lane; i < 64; i += 32) {
            float4 v = xb[i];
            int p = i * 4;
            int y = p >> 4, xx = p & 15;
            float* d = &sxw[(y + 1) * XSTRIDE + xx + 1];
            d[0] = v.x; d[1] = v.y; d[2] = v.z; d[3] = v.w;
        }
    }
    __syncthreads();   // sw01/scw4 CTA-wide, sx per-warp

    if (b >= nB) return;   // warp-uniform; no CTA barriers after this point

    float o0[NSTEP], o1[NSTEP];
    #pragma unroll
    for (int t = 0; t < NSTEP; t++) { o0[t] = 0.0f; o1[t] = 0.0f; }

    float* cw = call + warp * CAP;
    unsigned short* ciw = iall + warp * CAP;
    int cnt = 0;

    // exact scalar t-loop used only on (never-expected) capacity overflow
    auto fallb = [&](float cc, int ib) {
        float w0 = sw01[2 * ib], w1 = sw01[2 * ib + 1];
        float m = cc, s = setgt1(m);
        o0[0] = fmaf(s, w0, o0[0]); o1[0] = fmaf(s, w1, o1[0]);
        #pragma unroll
        for (int t = 1; t < NSTEP; t++) {
            m = fmaf(0.9f, m, cc);
            m -= s;
            s = setgt1(m);
            o0[t] = fmaf(s, w0, o0[t]); o1[t] = fmaf(s, w1, o1[t]);
        }
    };

    // ---------------- Phase 1: conv + classify + compact ----------------
    #pragma unroll 1
    for (int rr = 0; rr < 4; rr++) {
        const int q  = lane + 32 * rr;
        const int y  = q >> 3;
        const int x0 = (q & 7) * 2;
        const float* rp = sxw + y * XSTRIDE + x0;
        const float2 t00 = *(const float2*)(rp);
        const float2 t01 = *(const float2*)(rp + 2);
        const float2 t10 = *(const float2*)(rp + XSTRIDE);
        const float2 t11 = *(const float2*)(rp + XSTRIDE + 2);
        const float2 t20 = *(const float2*)(rp + 2 * XSTRIDE);
        const float2 t21 = *(const float2*)(rp + 2 * XSTRIDE + 2);

        const int qb = q * 2;

        #pragma unroll 1
        for (int ch = 0; ch < 8; ch++) {
            const float4* cw4 = (const float4*)&scw4[ch * 12];
            const float4 wA = cw4[0];
            const float4 wB = cw4[1];
            const float4 wC = cw4[2];

            float ca = wC.y, cb = wC.y;
            ca = fmaf(wA.x, t00.x, ca);  cb = fmaf(wA.x, t00.y, cb);
            ca = fmaf(wA.y, t00.y, ca);  cb = fmaf(wA.y, t01.x, cb);
            ca = fmaf(wA.z, t01.x, ca);  cb = fmaf(wA.z, t01.y, cb);
            ca = fmaf(wA.w, t10.x, ca);  cb = fmaf(wA.w, t10.y, cb);
            ca = fmaf(wB.x, t10.y, ca);  cb = fmaf(wB.x, t11.x, cb);
            ca = fmaf(wB.y, t11.x, ca);  cb = fmaf(wB.y, t11.y, cb);
            ca = fmaf(wB.z, t20.x, ca);  cb = fmaf(wB.z, t20.y, cb);
            ca = fmaf(wB.w, t20.y, ca);  cb = fmaf(wB.w, t21.x, cb);
            ca = fmaf(wC.x, t21.x, ca);  cb = fmaf(wC.x, t21.y, cb);

            const int ibA = ch * 256 + qb;
            const int ibB = ibA + 1;

            bool aA = ca > SKIP_THR;
            unsigned mAb = __ballot_sync(FULL, aA);
            int rA = cnt + __popc(mAb & lmlt);
            if (aA && rA < CAP) { cw[rA] = ca; ciw[rA] = (unsigned short)ibA; }
            cnt += __popc(mAb);

            bool aB = cb > SKIP_THR;
            unsigned mBb = __ballot_sync(FULL, aB);
            int rB = cnt + __popc(mBb & lmlt);
            if (aB && rB < CAP) { cw[rB] = cb; ciw[rB] = (unsigned short)ibB; }
            cnt += __popc(mBb);

            bool ovA = aA && (rA >= CAP);
            bool ovB = aB && (rB >= CAP);
            if (__any_sync(FULL, ovA || ovB)) {
                fallb(ovA ? ca : 0.0f, ovA ? ibA : 0);
                fallb(ovB ? cb : 0.0f, ovB ? ibB : 0);
            }
        }
    }
    __syncwarp();
    const int n = (cnt < CAP) ? cnt : CAP;

    // ---------------- Phase 2: recurrence over actives only ----------------
    #pragma unroll 1
    for (int base2 = 0; base2 < n; base2 += 64) {
        int i0 = base2 + lane;
        int i1 = i0 + 32;
        bool v0 = i0 < n, v1 = i1 < n;
        int i0c = v0 ? i0 : 0;
        int i1c = v1 ? i1 : 0;
        float cu = cw[i0c]; cu = v0 ? cu : 0.0f;   // c=0 pads are exact no-ops
        float cv = cw[i1c]; cv = v1 ? cv : 0.0f;
        int ju = ciw[i0c];
        int jv = ciw[i1c];
        const float2 wu = *(const float2*)&sw01[2 * ju];
        const float2 wq = *(const float2*)&sw01[2 * jv];

        // t = 0 peeled: m = c exactly
        float mu = cu, mv = cv;
        float su = setgt1(mu), sv = setgt1(mv);
        o0[0] = fmaf(su, wu.x, o0[0]); o1[0] = fmaf(su, wu.y, o1[0]);
        o0[0] = fmaf(sv, wq.x, o0[0]); o1[0] = fmaf(sv, wq.y, o1[0]);

        #pragma unroll
        for (int t = 1; t < NSTEP; t++) {
            mu = fmaf(0.9f, mu, cu);
            mv = fmaf(0.9f, mv, cv);
            mu -= su;
            mv -= sv;
            su = setgt1(mu);
            sv = setgt1(mv);
            o0[t] = fmaf(su, wu.x, o0[t]); o1[t] = fmaf(su, wu.y, o1[t]);
            o0[t] = fmaf(sv, wq.x, o0[t]); o1[t] = fmaf(sv, wq.y, o1[t]);
        }
    }

    // warp-reduce the 10 (out0, out1) partial sums
    #pragma unroll
    for (int off = 16; off > 0; off >>= 1) {
        #pragma unroll
        for (int t = 0; t < NSTEP; t++) {
            o0[t] += __shfl_down_sync(FULL, o0[t], off);
            o1[t] += __shfl_down_sync(FULL, o1[t], off);
        }
    }

    if (lane == 0) {
        const float fb0 = fcb[0], fb1 = fcb[1];
        float m20 = 0.f, m21 = 0.f, s20 = 0.f, s21 = 0.f, a0 = 0.f, a1 = 0.f;
        #pragma unroll
        for (int t = 0; t < NSTEP; t++) {
            float c0 = o0[t] + fb0;
            float c1 = o1[t] + fb1;
            m20 = fmaf(0.9f, m20, c0) - s20;
            m21 = fmaf(0.9f, m21, c1) - s21;
            s20 = (m20 > 1.0f) ? 1.0f : 0.0f;
            s21 = (m21 > 1.0f) ? 1.0f : 0.0f;
            a0 += s20;
            a1 += s21;
        }
        out[b * 2 + 0] = a0;
        out[b * 2 + 1] = a1;
    }
}

extern "C" void kernel_launch(void* const* d_in, const int* in_sizes, int n_in,
                              void* d_out, int out_size) {
    const float* x  = (const float*)d_in[0];
    const float* cwp = (const float*)d_in[1];
    const float* cbp = (const float*)d_in[2];
    const float* fw = (const float*)d_in[3];
    const float* fb = (const float*)d_in[4];
    float* out = (float*)d_out;

    const int nB = in_sizes[0] / 256;
    const int blocks = (nB + WARPS - 1) / WARPS;
    // 4096 + 96 + 4*864 + 4*CAP floats, plus 4*CAP u16
    const size_t smem = (size_t)(4096 + 96 + 4 * 864 + 4 * CAP) * 4
                      + (size_t)(4 * CAP) * 2;   // = 68992 bytes
    cudaFuncSetAttribute(snn_kernel,
                         cudaFuncAttributeMaxDynamicSharedMemorySize,
                         (int)smem);
    snn_kernel<<<blocks, THREADS, smem>>>(x, cwp, cbp, fw, fb, out, nB);
}

// round 9
// speedup vs baseline: 1.0192x; 1.0192x over previous
#include <cuda_runtime.h>

#define WARPS 4
#define THREADS 128
#define NSTEP 10
#define XSTRIDE 48        // floats per padded row; conflict-free LDS.64
#define LO_THR 0.1535f    // c <= LO  -> provably never spikes (c*6.51322 < 1)
#define HI_THR 1.096f     // c >= HI  -> provably spikes every step (t=9 bound 1.0941)

__device__ __forceinline__ float setgt1(float a) {
    float r;
    asm("set.gt.f32.f32 %0, %1, %2;" : "=f"(r) : "f"(a), "f"(1.0f));
    return r;
}

// One warp per sample, lane-private 3-way classification (no ballots):
//   c <= LO : never spikes, contributes exact +0 -> dropped.
//   c >= HI : spikes every step -> only its fc weights matter; key stored at
//             the BACK of the lane's list, weights folded into SA once.
//   middle  : full bit-exact 10-step recurrence, (c, key) stored at the FRONT
//             of the lane's column-major list.
// Phase 2 runs the t-loop only over middle elements (warp-max trip, c=0 pads
// are exact no-ops). fc weights fetched via __ldg (L1-resident 16KB).
__global__ void __launch_bounds__(THREADS)
snn_kernel(const float* __restrict__ x, const float* __restrict__ convw,
           const float* __restrict__ convb, const float* __restrict__ fcw,
           const float* __restrict__ fcb, float* __restrict__ out, int nB)
{
    extern __shared__ float dsm[];
    float* sxall = dsm;                    // 4 * 864 f: padded input tiles
    float* scw4  = sxall + 4 * 864;        // 96 f: per ch w0..w8, bias, pad
    float* call  = scw4 + 96;              // 4 * 64 * 32 f: per-lane c lists
    unsigned char* kall =
        (unsigned char*)(call + 4 * 2048); // 4 * 64 * 32 u8: 6-bit keys

    const int tid  = threadIdx.x;
    const int warp = tid >> 5;
    const int lane = tid & 31;
    const long long b = (long long)blockIdx.x * WARPS + warp;
    const unsigned FULL = 0xffffffffu;

    if (tid < 96) {
        int ch = tid / 12, k = tid % 12;
        float v = 0.0f;
        if (k < 9)       v = convw[ch * 9 + k];
        else if (k == 9) v = convb[ch];
        scw4[tid] = v;
    }

    float* sxw = sxall + warp * 864;
    for (int i = lane; i < 864; i += 32) sxw[i] = 0.0f;
    __syncwarp();
    if (b < nB) {
        const float4* xb = (const float4*)(x + b * 256);
        #pragma unroll
        for (int i = lane; i < 64; i += 32) {
            float4 v = xb[i];
            int p = i * 4;
            int y = p >> 4, xx = p & 15;
            float* d = &sxw[(y + 1) * XSTRIDE + xx + 1];
            d[0] = v.x; d[1] = v.y; d[2] = v.z; d[3] = v.w;
        }
    }
    __syncthreads();

    if (b >= nB) return;   // warp-uniform; no CTA barriers after this point

    float* cl = call + warp * 2048;        // [slot*32 + lane]
    unsigned char* kl = kall + warp * 2048;

    float o0[NSTEP], o1[NSTEP];
    #pragma unroll
    for (int t = 0; t < NSTEP; t++) { o0[t] = 0.0f; o1[t] = 0.0f; }
    float SA0 = 0.0f, SA1 = 0.0f;

    int cnt = 0, acnt = 0;

    // ---------------- Phase 1: conv + lane-private classify ----------------
    #pragma unroll 1
    for (int rr = 0; rr < 4; rr++) {
        const int q  = lane + 32 * rr;
        const int y  = q >> 3;
        const int x0 = (q & 7) * 2;
        const float* rp = sxw + y * XSTRIDE + x0;
        const float2 t00 = *(const float2*)(rp);
        const float2 t01 = *(const float2*)(rp + 2);
        const float2 t10 = *(const float2*)(rp + XSTRIDE);
        const float2 t11 = *(const float2*)(rp + XSTRIDE + 2);
        const float2 t20 = *(const float2*)(rp + 2 * XSTRIDE);
        const float2 t21 = *(const float2*)(rp + 2 * XSTRIDE + 2);

        #pragma unroll 1
        for (int ch = 0; ch < 8; ch++) {
            const float4* cw4 = (const float4*)&scw4[ch * 12];
            const float4 wA = cw4[0];
            const float4 wB = cw4[1];
            const float4 wC = cw4[2];

            // scalar conv, op order identical to R1/R4/R5/R7
            float ca = wC.y, cb = wC.y;
            ca = fmaf(wA.x, t00.x, ca);  cb = fmaf(wA.x, t00.y, cb);
            ca = fmaf(wA.y, t00.y, ca);  cb = fmaf(wA.y, t01.x, cb);
            ca = fmaf(wA.z, t01.x, ca);  cb = fmaf(wA.z, t01.y, cb);
            ca = fmaf(wA.w, t10.x, ca);  cb = fmaf(wA.w, t10.y, cb);
            ca = fmaf(wB.x, t10.y, ca);  cb = fmaf(wB.x, t11.x, cb);
            ca = fmaf(wB.y, t11.x, ca);  cb = fmaf(wB.y, t11.y, cb);
            ca = fmaf(wB.z, t20.x, ca);  cb = fmaf(wB.z, t20.y, cb);
            ca = fmaf(wB.w, t20.y, ca);  cb = fmaf(wB.w, t21.x, cb);
            ca = fmaf(wC.x, t21.x, ca);  cb = fmaf(wC.x, t21.y, cb);

            const int kbase = (ch << 3) | (rr << 1);
            // half 0
            {
                const float c = ca;
                const int k = kbase;
                if (c > LO_THR) {
                    if (c < HI_THR) {
                        cl[cnt * 32 + lane] = c;
                        kl[cnt * 32 + lane] = (unsigned char)k;
                        cnt++;
                    } else {
                        kl[(63 - acnt) * 32 + lane] = (unsigned char)k;
                        acnt++;
                    }
                }
            }
            // half 1
            {
                const float c = cb;
                const int k = kbase | 1;
                if (c > LO_THR) {
                    if (c < HI_THR) {
                        cl[cnt * 32 + lane] = c;
                        kl[cnt * 32 + lane] = (unsigned char)k;
                        cnt++;
                    } else {
                        kl[(63 - acnt) * 32 + lane] = (unsigned char)k;
                        acnt++;
                    }
                }
            }
        }
    }

    int maxn = cnt, maxa = acnt;
    #pragma unroll
    for (int off = 16; off > 0; off >>= 1) {
        maxn = max(maxn, __shfl_xor_sync(FULL, maxn, off));
        maxa = max(maxa, __shfl_xor_sync(FULL, maxa, off));
    }

    const int lane2 = lane * 2;

    // ---------------- Phase 2: recurrence over middle class ----------------
    #pragma unroll 1
    for (int i = 0; i < maxn; i += 2) {
        const bool v0 = i < cnt;
        const bool v1 = (i + 1) < cnt;
        float cu = cl[i * 32 + lane];        cu = v0 ? cu : 0.0f;  // pad: exact no-op
        float cv = cl[(i + 1) * 32 + lane];  cv = v1 ? cv : 0.0f;
        int ku = (int)kl[i * 32 + lane];        ku = v0 ? ku : 0;
        int kv = (int)kl[(i + 1) * 32 + lane];  kv = v1 ? kv : 0;
        const int ibu = ((ku >> 3) << 8) + (((ku >> 1) & 3) << 6) + lane2 + (ku & 1);
        const int ibv = ((kv >> 3) << 8) + (((kv >> 1) & 3) << 6) + lane2 + (kv & 1);
        const float w0u = __ldg(fcw + ibu);
        const float w1u = __ldg(fcw + 2048 + ibu);
        const float w0v = __ldg(fcw + ibv);
        const float w1v = __ldg(fcw + 2048 + ibv);

        // t = 0 peeled: m = c exactly
        float mu = cu, mv = cv;
        float su = setgt1(mu), sv = setgt1(mv);
        o0[0] = fmaf(su, w0u, o0[0]); o1[0] = fmaf(su, w1u, o1[0]);
        o0[0] = fmaf(sv, w0v, o0[0]); o1[0] = fmaf(sv, w1v, o1[0]);

        #pragma unroll
        for (int t = 1; t < NSTEP; t++) {
            mu = fmaf(0.9f, mu, cu);
            mv = fmaf(0.9f, mv, cv);
            mu -= su;                 // Sterbenz-exact for m in (1,2]
            mv -= sv;
            su = setgt1(mu);
            sv = setgt1(mv);
            o0[t] = fmaf(su, w0u, o0[t]); o1[t] = fmaf(su, w1u, o1[t]);
            o0[t] = fmaf(sv, w0v, o0[t]); o1[t] = fmaf(sv, w1v, o1[t]);
        }
    }

    // ---------------- Phase 2b: always-spiking class -> weight sums ----------------
    #pragma unroll 1
    for (int i = 0; i < maxa; i += 2) {
        const bool v0 = i < acnt;
        const bool v1 = (i + 1) < acnt;
        int ku = (int)kl[(63 - i) * 32 + lane];  ku = v0 ? ku : 0;
        int kv = (int)kl[(62 - i) * 32 + lane];  kv = v1 ? kv : 0;
        const int ibu = ((ku >> 3) << 8) + (((ku >> 1) & 3) << 6) + lane2 + (ku & 1);
        const int ibv = ((kv >> 3) << 8) + (((kv >> 1) & 3) << 6) + lane2 + (kv & 1);
        const float w0u = __ldg(fcw + ibu);
        const float w1u = __ldg(fcw + 2048 + ibu);
        const float w0v = __ldg(fcw + ibv);
        const float w1v = __ldg(fcw + 2048 + ibv);
        SA0 += v0 ? w0u : 0.0f;  SA1 += v0 ? w1u : 0.0f;
        SA0 += v1 ? w0v : 0.0f;  SA1 += v1 ? w1v : 0.0f;
    }

    // warp-reduce the 10 (out0, out1) partial sums + the always-sums
    #pragma unroll
    for (int off = 16; off > 0; off >>= 1) {
        #pragma unroll
        for (int t = 0; t < NSTEP; t++) {
            o0[t] += __shfl_down_sync(FULL, o0[t], off);
            o1[t] += __shfl_down_sync(FULL, o1[t], off);
        }
        SA0 += __shfl_down_sync(FULL, SA0, off);
        SA1 += __shfl_down_sync(FULL, SA1, off);
    }

    if (lane == 0) {
        const float fb0 = fcb[0], fb1 = fcb[1];
        float m20 = 0.f, m21 = 0.f, s20 = 0.f, s21 = 0.f, a0 = 0.f, a1 = 0.f;
        #pragma unroll
        for (int t = 0; t < NSTEP; t++) {
            float c0 = o0[t] + SA0 + fb0;   // always-class spikes at every t
            float c1 = o1[t] + SA1 + fb1;
            m20 = fmaf(0.9f, m20, c0) - s20;
            m21 = fmaf(0.9f, m21, c1) - s21;
            s20 = (m20 > 1.0f) ? 1.0f : 0.0f;
            s21 = (m21 > 1.0f) ? 1.0f : 0.0f;
            a0 += s20;
            a1 += s21;
        }
        out[b * 2 + 0] = a0;
        out[b * 2 + 1] = a1;
    }
}

extern "C" void kernel_launch(void* const* d_in, const int* in_sizes, int n_in,
                              void* d_out, int out_size) {
    const float* x   = (const float*)d_in[0];
    const float* cwp = (const float*)d_in[1];
    const float* cbp = (const float*)d_in[2];
    const float* fw  = (const float*)d_in[3];
    const float* fb  = (const float*)d_in[4];
    float* out = (float*)d_out;

    const int nB = in_sizes[0] / 256;
    const int blocks = (nB + WARPS - 1) / WARPS;
    // (4*864 + 96 + 4*2048) floats + 4*2048 bytes = 55168 bytes
    const size_t smem = (size_t)(4 * 864 + 96 + 4 * 2048) * 4 + (size_t)(4 * 2048);
    cudaFuncSetAttribute(snn_kernel,
                         cudaFuncAttributeMaxDynamicSharedMemorySize,
                         (int)smem);
    snn_kernel<<<blocks, THREADS, smem>>>(x, cwp, cbp, fw, fb, out, nB);
}

// round 10
// speedup vs baseline: 1.3493x; 1.3239x over previous
#include <cuda_runtime.h>

#define WARPS 8
#define THREADS 256
#define NSTEP 10
#define XSTRIDE 48   // floats per padded row; 48 % 32 == 16 -> conflict-free LDS.64

__device__ __forceinline__ float setgt1(float a) {
    float r;
    asm("set.gt.f32.f32 %0, %1, %2;" : "=f"(r) : "f"(a), "f"(1.0f));
    return r;
}

// R7 structure (best: 272.6us, issue 87.3%) with two bit-exact scheduling
// fixes: all four LDS.128 hoisted to the top of each (rr,ch) iteration so
// their latency hides under the conv FMA block, and the ch loop unrolled x2
// so ptxas can overlap one iteration's t-loop with the next one's loads.
// All arithmetic and summation order identical to R7.
__global__ void __launch_bounds__(THREADS, 4)
snn_kernel(const float* __restrict__ x, const float* __restrict__ convw,
           const float* __restrict__ convb, const float* __restrict__ fcw,
           const float* __restrict__ fcb, float* __restrict__ out, int nB)
{
    __shared__ __align__(16) float sx[WARPS][18 * XSTRIDE];
    __shared__ __align__(16) float sw01[4096];    // interleaved (w0_i, w1_i)
    __shared__ __align__(16) float scw4[8 * 12];  // per ch: w0..w8, bias, pad, pad

    const int tid  = threadIdx.x;
    const int warp = tid >> 5;
    const int lane = tid & 31;
    const long long b = (long long)blockIdx.x * WARPS + warp;

    for (int i = tid; i < 2048; i += THREADS) {
        sw01[2 * i]     = fcw[i];
        sw01[2 * i + 1] = fcw[2048 + i];
    }
    if (tid < 96) {
        int ch = tid / 12, k = tid % 12;
        float v = 0.0f;
        if (k < 9)       v = convw[ch * 9 + k];
        else if (k == 9) v = convb[ch];
        scw4[tid] = v;
    }

    float* sxw = sx[warp];
    #pragma unroll
    for (int i = lane; i < 18 * XSTRIDE; i += 32) sxw[i] = 0.0f;
    __syncwarp();

    if (b < nB) {
        const float4* xb = (const float4*)(x + b * 256);
        #pragma unroll
        for (int i = lane; i < 64; i += 32) {
            float4 v = xb[i];
            int p = i * 4;
            int y = p >> 4, xx = p & 15;
            float* d = &sxw[(y + 1) * XSTRIDE + xx + 1];
            d[0] = v.x; d[1] = v.y; d[2] = v.z; d[3] = v.w;
        }
    }
    __syncthreads();

    if (b < nB) {
        // 10 time steps x 2 output channels, scalar accumulators
        float o0[NSTEP], o1[NSTEP];
        #pragma unroll
        for (int t = 0; t < NSTEP; t++) { o0[t] = 0.0f; o1[t] = 0.0f; }

        #pragma unroll 1
        for (int rr = 0; rr < 4; rr++) {
            const int q  = lane + 32 * rr;   // pair index in channel
            const int y  = q >> 3;
            const int x0 = (q & 7) * 2;
            const float* rp = sxw + y * XSTRIDE + x0;
            // taps register-resident across the whole channel loop
            const float2 t00 = *(const float2*)(rp);
            const float2 t01 = *(const float2*)(rp + 2);
            const float2 t10 = *(const float2*)(rp + XSTRIDE);
            const float2 t11 = *(const float2*)(rp + XSTRIDE + 2);
            const float2 t20 = *(const float2*)(rp + 2 * XSTRIDE);
            const float2 t21 = *(const float2*)(rp + 2 * XSTRIDE + 2);

            const int qb = q * 2;            // flat even element within channel

            #pragma unroll 2
            for (int ch = 0; ch < 8; ch++) {
                // ---- all loads first: latency hides under the conv block ----
                const float4* cw4 = (const float4*)&scw4[ch * 12];
                const float4 wA = cw4[0];   // w0 w1 w2 w3
                const float4 wB = cw4[1];   // w4 w5 w6 w7
                const float4 wC = cw4[2];   // w8 bias - -
                const int ib = ch * 256 + qb;
                // wv = (w0_even, w1_even, w0_odd, w1_odd), one LDS.128
                const float4 wv = *(const float4*)&sw01[2 * ib];

                // scalar conv, op order identical to R1/R4/R5/R7
                float ca = wC.y, cb = wC.y;
                ca = fmaf(wA.x, t00.x, ca);  cb = fmaf(wA.x, t00.y, cb);
                ca = fmaf(wA.y, t00.y, ca);  cb = fmaf(wA.y, t01.x, cb);
                ca = fmaf(wA.z, t01.x, ca);  cb = fmaf(wA.z, t01.y, cb);
                ca = fmaf(wA.w, t10.x, ca);  cb = fmaf(wA.w, t10.y, cb);
                ca = fmaf(wB.x, t10.y, ca);  cb = fmaf(wB.x, t11.x, cb);
                ca = fmaf(wB.y, t11.x, ca);  cb = fmaf(wB.y, t11.y, cb);
                ca = fmaf(wB.z, t20.x, ca);  cb = fmaf(wB.z, t20.y, cb);
                ca = fmaf(wB.w, t20.y, ca);  cb = fmaf(wB.w, t21.x, cb);
                ca = fmaf(wC.x, t21.x, ca);  cb = fmaf(wC.x, t21.y, cb);

                // t = 0 peeled: m = 0.9*0 + c - 0 = c exactly
                float ma = ca, mb = cb;
                float sa = setgt1(ma);
                float sb = setgt1(mb);
                o0[0] = fmaf(sa, wv.x, o0[0]);
                o0[0] = fmaf(sb, wv.z, o0[0]);
                o1[0] = fmaf(sa, wv.y, o1[0]);
                o1[0] = fmaf(sb, wv.w, o1[0]);

                #pragma unroll
                for (int t = 1; t < NSTEP; t++) {
                    ma = fmaf(0.9f, ma, ca);   // beta*m + c   (FFMA)
                    mb = fmaf(0.9f, mb, cb);
                    ma = ma - sa;              // - reset      (FADD)
                    mb = mb - sb;
                    sa = setgt1(ma);           // spk = m > 1  (FSET, alu)
                    sb = setgt1(mb);
                    // acc order: even half then odd half, per accumulator
                    o0[t] = fmaf(sa, wv.x, o0[t]);
                    o0[t] = fmaf(sb, wv.z, o0[t]);
                    o1[t] = fmaf(sa, wv.y, o1[t]);
                    o1[t] = fmaf(sb, wv.w, o1[t]);
                }
            }
        }

        // warp-reduce the 10 (out0, out1) partial sums
        #pragma unroll
        for (int off = 16; off > 0; off >>= 1) {
            #pragma unroll
            for (int t = 0; t < NSTEP; t++) {
                o0[t] += __shfl_down_sync(0xffffffffu, o0[t], off);
                o1[t] += __shfl_down_sync(0xffffffffu, o1[t], off);
            }
        }

        if (lane == 0) {
            const float fb0 = fcb[0], fb1 = fcb[1];
            float m20 = 0.f, m21 = 0.f, s20 = 0.f, s21 = 0.f, a0 = 0.f, a1 = 0.f;
            #pragma unroll
            for (int t = 0; t < NSTEP; t++) {
                float c0 = o0[t] + fb0;
                float c1 = o1[t] + fb1;
                m20 = fmaf(0.9f, m20, c0) - s20;
                m21 = fmaf(0.9f, m21, c1) - s21;
                s20 = (m20 > 1.0f) ? 1.0f : 0.0f;
                s21 = (m21 > 1.0f) ? 1.0f : 0.0f;
                a0 += s20;
                a1 += s21;
            }
            out[b * 2 + 0] = a0;
            out[b * 2 + 1] = a1;
        }
    }
}

extern "C" void kernel_launch(void* const* d_in, const int* in_sizes, int n_in,
                              void* d_out, int out_size) {
    const float* x  = (const float*)d_in[0];
    const float* cw = (const float*)d_in[1];
    const float* cb = (const float*)d_in[2];
    const float* fw = (const float*)d_in[3];
    const float* fb = (const float*)d_in[4];
    float* out = (float*)d_out;

    const int nB = in_sizes[0] / 256;
    const int blocks = (nB + WARPS - 1) / WARPS;
    snn_kernel<<<blocks, THREADS>>>(x, cw, cb, fw, fb, out, nB);
}

// round 11
// speedup vs baseline: 1.3605x; 1.0083x over previous
#include <cuda_runtime.h>

#define WARPS 8
#define THREADS 256
#define NSTEP 10
#define XSTRIDE 48   // floats per padded row; 48 % 32 == 16 -> conflict-free LDS.64

__device__ __forceinline__ float setgt1(float a) {
    float r;
    asm("set.gt.f32.f32 %0, %1, %2;" : "=f"(r) : "f"(a), "f"(1.0f));
    return r;
}

// R10 structure (best: 270.8us, issue 88.1%) with the butterfly warp
// reduction replaced by a shared-memory transpose reduce in the dead input
// tile: stride-33 layout makes both the 20 partial stores and the 32-value
// row sums bank-conflict-free, cutting ~150 issue slots and the synchronized
// SHFL/MIO burst per warp. Main loop byte-identical to R10.
__global__ void __launch_bounds__(THREADS, 4)
snn_kernel(const float* __restrict__ x, const float* __restrict__ convw,
           const float* __restrict__ convb, const float* __restrict__ fcw,
           const float* __restrict__ fcb, float* __restrict__ out, int nB)
{
    __shared__ __align__(16) float sx[WARPS][18 * XSTRIDE];
    __shared__ __align__(16) float sw01[4096];    // interleaved (w0_i, w1_i)
    __shared__ __align__(16) float scw4[8 * 12];  // per ch: w0..w8, bias, pad, pad

    const int tid  = threadIdx.x;
    const int warp = tid >> 5;
    const int lane = tid & 31;
    const long long b = (long long)blockIdx.x * WARPS + warp;

    for (int i = tid; i < 2048; i += THREADS) {
        sw01[2 * i]     = fcw[i];
        sw01[2 * i + 1] = fcw[2048 + i];
    }
    if (tid < 96) {
        int ch = tid / 12, k = tid % 12;
        float v = 0.0f;
        if (k < 9)       v = convw[ch * 9 + k];
        else if (k == 9) v = convb[ch];
        scw4[tid] = v;
    }

    float* sxw = sx[warp];
    #pragma unroll
    for (int i = lane; i < 18 * XSTRIDE; i += 32) sxw[i] = 0.0f;
    __syncwarp();

    if (b < nB) {
        const float4* xb = (const float4*)(x + b * 256);
        #pragma unroll
        for (int i = lane; i < 64; i += 32) {
            float4 v = xb[i];
            int p = i * 4;
            int y = p >> 4, xx = p & 15;
            float* d = &sxw[(y + 1) * XSTRIDE + xx + 1];
            d[0] = v.x; d[1] = v.y; d[2] = v.z; d[3] = v.w;
        }
    }
    __syncthreads();

    if (b < nB) {
        // 10 time steps x 2 output channels, scalar accumulators
        float o0[NSTEP], o1[NSTEP];
        #pragma unroll
        for (int t = 0; t < NSTEP; t++) { o0[t] = 0.0f; o1[t] = 0.0f; }

        #pragma unroll 1
        for (int rr = 0; rr < 4; rr++) {
            const int q  = lane + 32 * rr;   // pair index in channel
            const int y  = q >> 3;
            const int x0 = (q & 7) * 2;
            const float* rp = sxw + y * XSTRIDE + x0;
            // taps register-resident across the whole channel loop
            const float2 t00 = *(const float2*)(rp);
            const float2 t01 = *(const float2*)(rp + 2);
            const float2 t10 = *(const float2*)(rp + XSTRIDE);
            const float2 t11 = *(const float2*)(rp + XSTRIDE + 2);
            const float2 t20 = *(const float2*)(rp + 2 * XSTRIDE);
            const float2 t21 = *(const float2*)(rp + 2 * XSTRIDE + 2);

            const int qb = q * 2;            // flat even element within channel

            #pragma unroll 2
            for (int ch = 0; ch < 8; ch++) {
                // ---- all loads first: latency hides under the conv block ----
                const float4* cw4 = (const float4*)&scw4[ch * 12];
                const float4 wA = cw4[0];   // w0 w1 w2 w3
                const float4 wB = cw4[1];   // w4 w5 w6 w7
                const float4 wC = cw4[2];   // w8 bias - -
                const int ib = ch * 256 + qb;
                // wv = (w0_even, w1_even, w0_odd, w1_odd), one LDS.128
                const float4 wv = *(const float4*)&sw01[2 * ib];

                // scalar conv, op order identical to R1/R4/R5/R7/R10
                float ca = wC.y, cb = wC.y;
                ca = fmaf(wA.x, t00.x, ca);  cb = fmaf(wA.x, t00.y, cb);
                ca = fmaf(wA.y, t00.y, ca);  cb = fmaf(wA.y, t01.x, cb);
                ca = fmaf(wA.z, t01.x, ca);  cb = fmaf(wA.z, t01.y, cb);
                ca = fmaf(wA.w, t10.x, ca);  cb = fmaf(wA.w, t10.y, cb);
                ca = fmaf(wB.x, t10.y, ca);  cb = fmaf(wB.x, t11.x, cb);
                ca = fmaf(wB.y, t11.x, ca);  cb = fmaf(wB.y, t11.y, cb);
                ca = fmaf(wB.z, t20.x, ca);  cb = fmaf(wB.z, t20.y, cb);
                ca = fmaf(wB.w, t20.y, ca);  cb = fmaf(wB.w, t21.x, cb);
                ca = fmaf(wC.x, t21.x, ca);  cb = fmaf(wC.x, t21.y, cb);

                // t = 0 peeled: m = 0.9*0 + c - 0 = c exactly
                float ma = ca, mb = cb;
                float sa = setgt1(ma);
                float sb = setgt1(mb);
                o0[0] = fmaf(sa, wv.x, o0[0]);
                o0[0] = fmaf(sb, wv.z, o0[0]);
                o1[0] = fmaf(sa, wv.y, o1[0]);
                o1[0] = fmaf(sb, wv.w, o1[0]);

                #pragma unroll
                for (int t = 1; t < NSTEP; t++) {
                    ma = fmaf(0.9f, ma, ca);   // beta*m + c   (FFMA)
                    mb = fmaf(0.9f, mb, cb);
                    ma = ma - sa;              // - reset      (FADD)
                    mb = mb - sb;
                    sa = setgt1(ma);           // spk = m > 1  (FSET, alu)
                    sb = setgt1(mb);
                    // acc order: even half then odd half, per accumulator
                    o0[t] = fmaf(sa, wv.x, o0[t]);
                    o0[t] = fmaf(sb, wv.z, o0[t]);
                    o1[t] = fmaf(sa, wv.y, o1[t]);
                    o1[t] = fmaf(sb, wv.w, o1[t]);
                }
            }
        }

        // ---- smem-transpose warp reduction (input tile sxw is dead now) ----
        // layout stride 33: slot r (0..19), lane l -> sxw[r*33 + l]
        // banks (r + l) % 32: conflict-free stores (fixed r per STS) and
        // conflict-free row sums (fixed j across lanes r).
        __syncwarp();
        #pragma unroll
        for (int t = 0; t < NSTEP; t++) {
            sxw[t * 33 + lane]            = o0[t];
            sxw[(NSTEP + t) * 33 + lane]  = o1[t];
        }
        __syncwarp();
        if (lane < 2 * NSTEP) {
            const float* p = &sxw[lane * 33];
            float tot = 0.0f;
            #pragma unroll
            for (int j = 0; j < 32; j++) tot += p[j];
            sxw[20 * 33 + lane] = tot;
        }
        __syncwarp();

        if (lane == 0) {
            const float fb0 = fcb[0], fb1 = fcb[1];
            float m20 = 0.f, m21 = 0.f, s20 = 0.f, s21 = 0.f, a0 = 0.f, a1 = 0.f;
            #pragma unroll
            for (int t = 0; t < NSTEP; t++) {
                float c0 = sxw[20 * 33 + t]         + fb0;
                float c1 = sxw[20 * 33 + NSTEP + t] + fb1;
                m20 = fmaf(0.9f, m20, c0) - s20;
                m21 = fmaf(0.9f, m21, c1) - s21;
                s20 = (m20 > 1.0f) ? 1.0f : 0.0f;
                s21 = (m21 > 1.0f) ? 1.0f : 0.0f;
                a0 += s20;
                a1 += s21;
            }
            out[b * 2 + 0] = a0;
            out[b * 2 + 1] = a1;
        }
    }
}

extern "C" void kernel_launch(void* const* d_in, const int* in_sizes, int n_in,
                              void* d_out, int out_size) {
    const float* x  = (const float*)d_in[0];
    const float* cw = (const float*)d_in[1];
    const float* cb = (const float*)d_in[2];
    const float* fw = (const float*)d_in[3];
    const float* fb = (const float*)d_in[4];
    float* out = (float*)d_out;

    const int nB = in_sizes[0] / 256;
    const int blocks = (nB + WARPS - 1) / WARPS;
    snn_kernel<<<blocks, THREADS>>>(x, cw, cb, fw, fb, out, nB);
}